// round 1
// baseline (speedup 1.0000x reference)
#include <cuda_runtime.h>
#include <math.h>

#define SR    16000
#define WIN   400
#define HOP   160
#define NFFT  512
#define NBIN  257      // NFFT/2 + 1
#define NMELS 40
#define NMFCC 13
#define BATCH 64
#define LEN   160000
#define NF    998      // (LEN - WIN)/HOP + 1
#define OUTC  39       // 3 * NMFCC

#ifndef M_PI
#define M_PI 3.14159265358979323846
#endif

// -------- constant tables (built on device each launch; deterministic) --------
__device__ float  d_window[WIN];
__device__ float2 d_tw[NFFT / 2];              // exp(-2*pi*i*j/512)
__device__ float  d_fbank[NMELS][NBIN];
__device__ int    d_klo[NMELS];
__device__ int    d_khi[NMELS];
__device__ float  d_dct[NMELS][NMELS];

__global__ void init_consts_kernel() {
    const int t = threadIdx.x;
    const int nt = blockDim.x;

    // Hamming window (periodic, torch default): 0.54 - 0.46*cos(2*pi*n/WIN)
    for (int n = t; n < WIN; n += nt)
        d_window[n] = (float)(0.54 - 0.46 * cos(2.0 * M_PI * (double)n / (double)WIN));

    // FFT twiddles (double precision, cast to float)
    for (int j = t; j < NFFT / 2; j += nt) {
        double a = -2.0 * M_PI * (double)j / (double)NFFT;
        d_tw[j] = make_float2((float)cos(a), (float)sin(a));
    }

    // Mel filterbank: replicate numpy float64 math exactly (floor on f64)
    __shared__ double bins[NMELS + 2];
    if (t < NMELS + 2) {
        double high_mel = 2595.0 * log10(1.0 + (SR / 2.0) / 700.0);
        double mel = high_mel * ((double)t / (double)(NMELS + 1));   // linspace(0, high, 42)
        double hz = 700.0 * (pow(10.0, mel / 2595.0) - 1.0);
        bins[t] = floor((double)(NFFT + 1) * hz / (double)SR);
    }
    __syncthreads();

    for (int i = t; i < NMELS * NBIN; i += nt)
        ((float*)d_fbank)[i] = 0.0f;
    __syncthreads();

    if (t < NMELS) {
        int m = t + 1;
        int f_lo = (int)bins[m - 1], f_c = (int)bins[m], f_hi = (int)bins[m + 1];
        for (int k = f_lo; k < f_c; k++)
            d_fbank[t][k] = (float)(((double)k - bins[m - 1]) / (double)(f_c - f_lo));
        for (int k = f_c; k < f_hi; k++)
            d_fbank[t][k] = (float)((bins[m + 1] - (double)k) / (double)(f_hi - f_c));
        d_klo[t] = f_lo;
        d_khi[t] = f_hi;
    }

    // DCT-II ortho: [K, N]
    for (int i = t; i < NMELS * NMELS; i += nt) {
        int k = i / NMELS, n = i % NMELS;
        double c = cos(M_PI * (double)k * (2.0 * n + 1.0) / (2.0 * NMELS));
        double sc = (k == 0) ? sqrt(1.0 / NMELS) : sqrt(2.0 / NMELS);
        ((float*)d_dct)[i] = (float)(sc * c);
    }
}

// -------- main kernel: one CTA per frame --------
__global__ __launch_bounds__(128) void mfcc_kernel(const float* __restrict__ x,
                                                   float* __restrict__ out) {
    __shared__ float2 data[NFFT];
    __shared__ float  mag[NBIN];
    __shared__ float  logmel[NMELS];
    __shared__ float  mfcc[NMELS];
    __shared__ float  d1s[NMELS];

    const int fid = blockIdx.x;              // 0 .. BATCH*NF-1
    const int b = fid / NF;
    const int f = fid - b * NF;
    const float* __restrict__ xb = x + (size_t)b * LEN;
    const int base = f * HOP;
    const int t = threadIdx.x;

    // load + pre-emphasis + window + zero-pad, into bit-reversed positions
    for (int n = t; n < NFFT; n += 128) {
        float v = 0.0f;
        if (n < WIN) {
            int s = base + n;
            float cur = xb[s];
            float pre = (s == 0) ? cur : (cur - 0.97f * xb[s - 1]);
            v = pre * d_window[n];
        }
        int r = (int)(__brev((unsigned)n) >> 23);   // 9-bit reversal
        data[r] = make_float2(v, 0.0f);
    }
    __syncthreads();

    // radix-2 DIT, 9 stages
    #pragma unroll
    for (int s = 1; s <= 9; s++) {
        const int half = 1 << (s - 1);
        const int shift = 9 - s;
        for (int j = t; j < NFFT / 2; j += 128) {
            int grp = j >> (s - 1);
            int k = j & (half - 1);
            int i0 = (grp << s) + k;
            int i1 = i0 + half;
            float2 w = d_tw[k << shift];
            float2 a = data[i0], bb = data[i1];
            float tr = w.x * bb.x - w.y * bb.y;
            float ti = w.x * bb.y + w.y * bb.x;
            data[i0] = make_float2(a.x + tr, a.y + ti);
            data[i1] = make_float2(a.x - tr, a.y - ti);
        }
        __syncthreads();
    }

    // magnitude spectrum
    for (int k = t; k < NBIN; k += 128) {
        float2 v = data[k];
        mag[k] = sqrtf(v.x * v.x + v.y * v.y);
    }
    __syncthreads();

    // mel filterbank (sparse triangular) + log
    if (t < NMELS) {
        float acc = 0.0f;
        const int klo = d_klo[t], khi = d_khi[t];
        const float* __restrict__ fb = d_fbank[t];
        for (int k = klo; k < khi; k++)
            acc = fmaf(fb[k], mag[k], acc);
        logmel[t] = logf(acc + 1e-20f);
    }
    __syncthreads();

    // DCT-II ortho
    if (t < NMELS) {
        float acc = 0.0f;
        const float* __restrict__ dr = d_dct[t];
        #pragma unroll
        for (int n = 0; n < NMELS; n++)
            acc = fmaf(dr[n], logmel[n], acc);
        mfcc[t] = acc;
    }
    __syncthreads();

    // first delta over the 40 coefficients (zeros at edges)
    if (t < NMELS)
        d1s[t] = (t >= 1 && t <= NMELS - 2) ? 0.5f * (mfcc[t + 1] - mfcc[t - 1]) : 0.0f;
    __syncthreads();

    // write [mfcc[0:13], d1[0:13], d2[0:13]]
    float* __restrict__ ob = out + (size_t)fid * OUTC;
    if (t < NMFCC) {
        ob[t] = mfcc[t];
    } else if (t < 2 * NMFCC) {
        ob[t] = d1s[t - NMFCC];
    } else if (t < 3 * NMFCC) {
        int c = t - 2 * NMFCC;
        float d2 = (c >= 1) ? 0.5f * (d1s[c + 1] - d1s[c - 1]) : 0.0f;
        ob[t] = d2;
    }
}

extern "C" void kernel_launch(void* const* d_in, const int* in_sizes, int n_in,
                              void* d_out, int out_size) {
    (void)in_sizes; (void)n_in; (void)out_size;
    const float* x = (const float*)d_in[0];
    float* out = (float*)d_out;
    init_consts_kernel<<<1, 256>>>();
    mfcc_kernel<<<BATCH * NF, 128>>>(x, out);
}

// round 2
// speedup vs baseline: 2.3456x; 2.3456x over previous
#include <cuda_runtime.h>
#include <math.h>

#define SR    16000
#define WIN   400
#define HOP   160
#define NFFT  512
#define NBIN  257
#define NMELS 40
#define NMFCC 13
#define BATCH 64
#define LEN   160000
#define NF    998
#define OUTC  39
#define NPAIR (BATCH * NF / 2)   // 31936 packed FFTs
#define GROUPS 2                 // FFT groups (64 thr each) per CTA
#define THREADS (GROUPS * 64)

#ifndef M_PI
#define M_PI 3.14159265358979323846
#endif

// ---------------- constant tables (device-built; deterministic) ----------------
__device__ float  d_window[WIN];
__device__ float2 d_tw512[512];   // [t*8+s] = exp(-2*pi*i*t*s/512), t<64, s<8
__device__ float2 d_tw64[64];     // [n*8+s] = exp(-2*pi*i*n*s/64),  n,s<8
__device__ float  d_fbank[NMELS][NBIN];
__device__ int    d_klo[NMELS];
__device__ int    d_khi[NMELS];
__device__ float  d_dct[NMELS][NMELS];

__global__ void init_consts_kernel() {
    const int t = threadIdx.x, nt = blockDim.x;

    for (int n = t; n < WIN; n += nt)
        d_window[n] = (float)(0.54 - 0.46 * cos(2.0 * M_PI * (double)n / (double)WIN));

    for (int i = t; i < 512; i += nt) {
        int tt = i >> 3, s = i & 7;
        double a = -2.0 * M_PI * (double)(tt * s) / 512.0;
        d_tw512[i] = make_float2((float)cos(a), (float)sin(a));
    }
    for (int i = t; i < 64; i += nt) {
        int n = i >> 3, s = i & 7;
        double a = -2.0 * M_PI * (double)(n * s) / 64.0;
        d_tw64[i] = make_float2((float)cos(a), (float)sin(a));
    }

    __shared__ double bins[NMELS + 2];
    if (t < NMELS + 2) {
        double high_mel = 2595.0 * log10(1.0 + (SR / 2.0) / 700.0);
        double mel = high_mel * ((double)t / (double)(NMELS + 1));
        double hz = 700.0 * (pow(10.0, mel / 2595.0) - 1.0);
        bins[t] = floor((double)(NFFT + 1) * hz / (double)SR);
    }
    __syncthreads();
    for (int i = t; i < NMELS * NBIN; i += nt) ((float*)d_fbank)[i] = 0.0f;
    __syncthreads();
    if (t < NMELS) {
        int m = t + 1;
        int f_lo = (int)bins[m - 1], f_c = (int)bins[m], f_hi = (int)bins[m + 1];
        for (int k = f_lo; k < f_c; k++)
            d_fbank[t][k] = (float)(((double)k - bins[m - 1]) / (double)(f_c - f_lo));
        for (int k = f_c; k < f_hi; k++)
            d_fbank[t][k] = (float)((bins[m + 1] - (double)k) / (double)(f_hi - f_c));
        d_klo[t] = f_lo;
        d_khi[t] = f_hi;
    }
    for (int i = t; i < NMELS * NMELS; i += nt) {
        int k = i / NMELS, n = i % NMELS;
        double c = cos(M_PI * (double)k * (2.0 * n + 1.0) / (2.0 * NMELS));
        double sc = (k == 0) ? sqrt(1.0 / NMELS) : sqrt(2.0 / NMELS);
        ((float*)d_dct)[i] = (float)(sc * c);
    }
}

// ---------------- complex helpers ----------------
__device__ __forceinline__ float2 cadd(float2 a, float2 b) { return make_float2(a.x + b.x, a.y + b.y); }
__device__ __forceinline__ float2 csub(float2 a, float2 b) { return make_float2(a.x - b.x, a.y - b.y); }
__device__ __forceinline__ float2 cmul(float2 a, float2 b) {
    return make_float2(a.x * b.x - a.y * b.y, a.x * b.y + a.y * b.x);
}
__device__ __forceinline__ float2 negi(float2 a) { return make_float2(a.y, -a.x); }  // -i*a

// In-place 8-point DFT: v[s] <- sum_j v[j] * exp(-2*pi*i*j*s/8)
__device__ __forceinline__ void dft8(float2 v[8]) {
    const float c = 0.70710678118654752f;
    float2 t0 = cadd(v[0], v[4]), t1 = csub(v[0], v[4]);
    float2 t2 = cadd(v[2], v[6]), t3 = csub(v[2], v[6]);
    float2 E0 = cadd(t0, t2), E2 = csub(t0, t2);
    float2 t3n = negi(t3);
    float2 E1 = cadd(t1, t3n), E3 = csub(t1, t3n);
    float2 u0 = cadd(v[1], v[5]), u1 = csub(v[1], v[5]);
    float2 u2 = cadd(v[3], v[7]), u3 = csub(v[3], v[7]);
    float2 O0 = cadd(u0, u2), O2 = csub(u0, u2);
    float2 u3n = negi(u3);
    float2 O1 = cadd(u1, u3n), O3 = csub(u1, u3n);
    O1 = make_float2(c * (O1.x + O1.y), c * (O1.y - O1.x));   // * (c,-c)
    O2 = negi(O2);                                            // * -i
    O3 = make_float2(c * (O3.y - O3.x), -c * (O3.x + O3.y));  // * (-c,-c)
    v[0] = cadd(E0, O0); v[4] = csub(E0, O0);
    v[1] = cadd(E1, O1); v[5] = csub(E1, O1);
    v[2] = cadd(E2, O2); v[6] = csub(E2, O2);
    v[3] = cadd(E3, O3); v[7] = csub(E3, O3);
}

// ---------------- main kernel: 64 threads per packed FFT (2 frames) ----------------
__global__ __launch_bounds__(THREADS) void mfcc_kernel(const float* __restrict__ x,
                                                       float* __restrict__ out) {
    // Exchange buffers (also hold final spectrum). Max addr used: 72*7+63 = 567.
    __shared__ float sRe[GROUPS][568];
    __shared__ float sIm[GROUPS][568];
    __shared__ float sMag[GROUPS][2][NBIN];
    __shared__ float sMel[GROUPS][2][NMELS];
    __shared__ float sMfcc[GROUPS][2][NMELS];
    __shared__ float sD1[GROUPS][2][NMELS];

    const int lt  = threadIdx.x & 63;
    const int grp = threadIdx.x >> 6;
    const int p   = blockIdx.x * GROUPS + grp;        // packed-FFT id, < NPAIR
    const int b   = p / (NF / 2);
    const int fp  = p - b * (NF / 2);
    const int f0  = 2 * fp;
    const size_t row = (size_t)b * LEN;
    const int base0 = f0 * HOP;                       // row-local start of frame f0

    float2 v[8];

    // ---- load + pre-emphasis + window; frame f0 -> real, f0+1 -> imag ----
    #pragma unroll
    for (int j = 0; j < 8; j++) {
        int n = lt + 64 * j;
        if (n < WIN) {
            float w = d_window[n];
            int i0 = base0 + n;
            float a0 = x[row + i0];
            float p0 = (i0 == 0) ? a0 : (a0 - 0.97f * x[row + i0 - 1]);
            int i1 = i0 + HOP;                        // frame f0+1, i1 >= 160 > 0
            float a1 = x[row + i1];
            float p1 = a1 - 0.97f * x[row + i1 - 1];
            v[j] = make_float2(p0 * w, p1 * w);
        } else {
            v[j] = make_float2(0.0f, 0.0f);
        }
    }

    // ---- stage 1: radix-8 over stride 64, then twiddle W512^(t*s) ----
    dft8(v);
    #pragma unroll
    for (int s = 1; s < 8; s++) v[s] = cmul(v[s], d_tw512[lt * 8 + s]);

    // exchange 1: store z_s[t] at 72*s + t ; read z_s[n'' + 8j']
    #pragma unroll
    for (int s = 0; s < 8; s++) { sRe[grp][72 * s + lt] = v[s].x; sIm[grp][72 * s + lt] = v[s].y; }
    __syncthreads();
    {
        const int s = lt >> 3, npp = lt & 7;
        #pragma unroll
        for (int j = 0; j < 8; j++) {
            int a = 72 * s + npp + 8 * j;
            v[j] = make_float2(sRe[grp][a], sIm[grp][a]);
        }
        __syncthreads();

        // ---- stage 2: radix-8 over j', twiddle w64^(n''*s') ----
        dft8(v);
        #pragma unroll
        for (int sp = 1; sp < 8; sp++) v[sp] = cmul(v[sp], d_tw64[npp * 8 + sp]);

        // exchange 2: store v_{s,s',n''} at 68*n'' + 8*s' + s
        #pragma unroll
        for (int sp = 0; sp < 8; sp++) {
            int a = 68 * npp + 8 * sp + s;
            sRe[grp][a] = v[sp].x; sIm[grp][a] = v[sp].y;
        }
    }
    __syncthreads();
    {
        const int sp = lt >> 3, s = lt & 7;           // this thread -> outputs X[64m' + 8sp + s]
        #pragma unroll
        for (int j = 0; j < 8; j++) {
            int a = 68 * j + 8 * sp + s;
            v[j] = make_float2(sRe[grp][a], sIm[grp][a]);
        }
        __syncthreads();

        // ---- stage 3: radix-8 over n'' -> X[64*m' + lt] ----
        dft8(v);
        #pragma unroll
        for (int m = 0; m < 8; m++) { sRe[grp][72 * m + lt] = v[m].x; sIm[grp][72 * m + lt] = v[m].y; }
    }
    __syncthreads();

    // ---- unpack conjugate symmetry -> magnitudes for both frames ----
    for (int k = lt; k < NBIN; k += 64) {
        int a1 = 72 * (k >> 6) + (k & 63);
        int kk = (NFFT - k) & (NFFT - 1);
        int a2 = 72 * (kk >> 6) + (kk & 63);
        float ux = sRe[grp][a1], uy = sIm[grp][a1];
        float wx = sRe[grp][a2], wy = sIm[grp][a2];
        float Ar = 0.5f * (ux + wx), Ai = 0.5f * (uy - wy);
        float Br = 0.5f * (uy + wy), Bi = 0.5f * (wx - ux);
        sMag[grp][0][k] = sqrtf(Ar * Ar + Ai * Ai);
        sMag[grp][1][k] = sqrtf(Br * Br + Bi * Bi);
    }
    __syncthreads();

    // ---- mel filterbank + log (80 tasks over 64 threads) ----
    #pragma unroll
    for (int i = lt; i < 2 * NMELS; i += 64) {
        int fr = i / NMELS, m = i - fr * NMELS;
        float acc = 0.0f;
        const int klo = d_klo[m], khi = d_khi[m];
        const float* __restrict__ fb = d_fbank[m];
        const float* __restrict__ mg = sMag[grp][fr];
        for (int k = klo; k < khi; k++) acc = fmaf(fb[k], mg[k], acc);
        sMel[grp][fr][m] = logf(acc + 1e-20f);
    }
    __syncthreads();

    // ---- DCT-II ortho ----
    #pragma unroll
    for (int i = lt; i < 2 * NMELS; i += 64) {
        int fr = i / NMELS, m = i - fr * NMELS;
        float acc = 0.0f;
        const float* __restrict__ dr = d_dct[m];
        const float* __restrict__ ml = sMel[grp][fr];
        #pragma unroll
        for (int n = 0; n < NMELS; n++) acc = fmaf(dr[n], ml[n], acc);
        sMfcc[grp][fr][m] = acc;
    }
    __syncthreads();

    // ---- delta over coefficient axis ----
    #pragma unroll
    for (int i = lt; i < 2 * NMELS; i += 64) {
        int fr = i / NMELS, m = i - fr * NMELS;
        sD1[grp][fr][m] = (m >= 1 && m <= NMELS - 2)
                        ? 0.5f * (sMfcc[grp][fr][m + 1] - sMfcc[grp][fr][m - 1]) : 0.0f;
    }
    __syncthreads();

    // ---- write [mfcc[0:13], d1[0:13], d2[0:13]] for both frames ----
    #pragma unroll
    for (int i = lt; i < 2 * OUTC; i += 64) {
        int fr = i / OUTC, c = i - fr * OUTC;
        int frame = b * NF + f0 + fr;
        float val;
        if (c < NMFCC) {
            val = sMfcc[grp][fr][c];
        } else if (c < 2 * NMFCC) {
            val = sD1[grp][fr][c - NMFCC];
        } else {
            int cc = c - 2 * NMFCC;
            val = (cc >= 1) ? 0.5f * (sD1[grp][fr][cc + 1] - sD1[grp][fr][cc - 1]) : 0.0f;
        }
        out[(size_t)frame * OUTC + c] = val;
    }
}

extern "C" void kernel_launch(void* const* d_in, const int* in_sizes, int n_in,
                              void* d_out, int out_size) {
    (void)in_sizes; (void)n_in; (void)out_size;
    const float* x = (const float*)d_in[0];
    float* out = (float*)d_out;
    init_consts_kernel<<<1, 256>>>();
    mfcc_kernel<<<NPAIR / GROUPS, THREADS>>>(x, out);
}

// round 3
// speedup vs baseline: 4.7582x; 2.0285x over previous
#include <cuda_runtime.h>
#include <math.h>

#define SR    16000
#define WIN   400
#define HOP   160
#define NFFT  512
#define NBIN  257
#define NMELS 40
#define NMFCC 13
#define BATCH 64
#define LEN   160000
#define NF    998
#define OUTC  39
#define NPAIR (BATCH * NF / 2)   // 31936 packed FFTs
#define GROUPS 2                 // FFT groups (64 thr each) per CTA
#define THREADS (GROUPS * 64)
#define NDCT  16                 // only mfcc[0..14] are ever needed

#ifndef M_PI
#define M_PI 3.14159265358979323846
#endif

// ---------------- constant tables (device-built; deterministic) ----------------
__device__ float d_window[WIN];
__device__ float d_fbw[NMELS * 33];   // packed sparse mel weights, stride 33
__device__ int   d_klo[NMELS];
__device__ int   d_flen[NMELS];
__device__ float d_dct16[NDCT * 41];  // first 16 DCT rows, stride 41

__global__ void init_consts_kernel() {
    const int t = threadIdx.x, nt = blockDim.x;

    for (int n = t; n < WIN; n += nt)
        d_window[n] = (float)(0.54 - 0.46 * cos(2.0 * M_PI * (double)n / (double)WIN));

    __shared__ double bins[NMELS + 2];
    if (t < NMELS + 2) {
        double high_mel = 2595.0 * log10(1.0 + (SR / 2.0) / 700.0);
        double mel = high_mel * ((double)t / (double)(NMELS + 1));
        double hz = 700.0 * (pow(10.0, mel / 2595.0) - 1.0);
        bins[t] = floor((double)(NFFT + 1) * hz / (double)SR);
    }
    __syncthreads();
    for (int i = t; i < NMELS * 33; i += nt) d_fbw[i] = 0.0f;
    __syncthreads();
    if (t < NMELS) {
        int m = t + 1;
        int f_lo = (int)bins[m - 1], f_c = (int)bins[m], f_hi = (int)bins[m + 1];
        for (int k = f_lo; k < f_c; k++) {
            int j = k - f_lo;
            if (j < 33) d_fbw[t * 33 + j] = (float)(((double)k - bins[m - 1]) / (double)(f_c - f_lo));
        }
        for (int k = f_c; k < f_hi; k++) {
            int j = k - f_lo;
            if (j < 33) d_fbw[t * 33 + j] = (float)((bins[m + 1] - (double)k) / (double)(f_hi - f_c));
        }
        d_klo[t]  = f_lo;
        int len = f_hi - f_lo;
        d_flen[t] = len > 33 ? 33 : len;
    }
    for (int i = t; i < NDCT * 41; i += nt) {
        int k = i / 41, n = i % 41;
        float val = 0.0f;
        if (n < NMELS) {
            double c = cos(M_PI * (double)k * (2.0 * n + 1.0) / (2.0 * NMELS));
            double sc = (k == 0) ? sqrt(1.0 / NMELS) : sqrt(2.0 / NMELS);
            val = (float)(sc * c);
        }
        d_dct16[i] = val;
    }
}

// ---------------- complex helpers ----------------
__device__ __forceinline__ float2 cadd(float2 a, float2 b) { return make_float2(a.x + b.x, a.y + b.y); }
__device__ __forceinline__ float2 csub(float2 a, float2 b) { return make_float2(a.x - b.x, a.y - b.y); }
__device__ __forceinline__ float2 cmul(float2 a, float2 b) {
    return make_float2(a.x * b.x - a.y * b.y, a.x * b.y + a.y * b.x);
}
__device__ __forceinline__ float2 negi(float2 a) { return make_float2(a.y, -a.x); }  // -i*a

// In-place 8-point DFT
__device__ __forceinline__ void dft8(float2 v[8]) {
    const float c = 0.70710678118654752f;
    float2 t0 = cadd(v[0], v[4]), t1 = csub(v[0], v[4]);
    float2 t2 = cadd(v[2], v[6]), t3 = csub(v[2], v[6]);
    float2 E0 = cadd(t0, t2), E2 = csub(t0, t2);
    float2 t3n = negi(t3);
    float2 E1 = cadd(t1, t3n), E3 = csub(t1, t3n);
    float2 u0 = cadd(v[1], v[5]), u1 = csub(v[1], v[5]);
    float2 u2 = cadd(v[3], v[7]), u3 = csub(v[3], v[7]);
    float2 O0 = cadd(u0, u2), O2 = csub(u0, u2);
    float2 u3n = negi(u3);
    float2 O1 = cadd(u1, u3n), O3 = csub(u1, u3n);
    O1 = make_float2(c * (O1.x + O1.y), c * (O1.y - O1.x));
    O2 = negi(O2);
    O3 = make_float2(c * (O3.y - O3.x), -c * (O3.x + O3.y));
    v[0] = cadd(E0, O0); v[4] = csub(E0, O0);
    v[1] = cadd(E1, O1); v[5] = csub(E1, O1);
    v[2] = cadd(E2, O2); v[6] = csub(E2, O2);
    v[3] = cadd(E3, O3); v[7] = csub(E3, O3);
}

// ---------------- main kernel: 64 threads per packed FFT (2 frames) ----------------
__global__ __launch_bounds__(THREADS) void mfcc_kernel(const float* __restrict__ x,
                                                       float* __restrict__ out) {
    __shared__ float2 sZ[GROUPS][568];            // exchange buffer (strides 72 / 66)
    __shared__ float  sMag[GROUPS][2][264];
    __shared__ float  sMel[GROUPS][2][NMELS];
    __shared__ float  sMfcc[GROUPS][2][NDCT];
    __shared__ float  sD1[GROUPS][2][NDCT];
    __shared__ float  sFbw[NMELS * 33];
    __shared__ int    sKlo[NMELS];
    __shared__ int    sLen[NMELS];
    __shared__ float  sDct[NDCT * 41];

    const int tid = threadIdx.x;
    const int lt  = tid & 63;
    const int grp = tid >> 6;
    const int p   = blockIdx.x * GROUPS + grp;
    const int b   = p / (NF / 2);
    const int fp  = p - b * (NF / 2);
    const int f0  = 2 * fp;
    const size_t row = (size_t)b * LEN;
    const int base0 = f0 * HOP;

    // cooperative table staging (coalesced); first __syncthreads below covers it
    for (int i = tid; i < NMELS * 33; i += THREADS) sFbw[i] = d_fbw[i];
    for (int i = tid; i < NDCT * 41;  i += THREADS) sDct[i] = d_dct16[i];
    if (tid < NMELS) { sKlo[tid] = d_klo[tid]; sLen[tid] = d_flen[tid]; }

    float2 v[8];

    // ---- load + pre-emphasis + window; frame f0 -> real, f0+1 -> imag ----
    #pragma unroll
    for (int j = 0; j < 8; j++) {
        int n = lt + 64 * j;
        if (n < WIN) {
            float w = d_window[n];
            int i0 = base0 + n;
            float a0 = x[row + i0];
            float p0 = (i0 == 0) ? a0 : (a0 - 0.97f * x[row + i0 - 1]);
            int i1 = i0 + HOP;
            float a1 = x[row + i1];
            float p1 = a1 - 0.97f * x[row + i1 - 1];
            v[j] = make_float2(p0 * w, p1 * w);
        } else {
            v[j] = make_float2(0.0f, 0.0f);
        }
    }

    // ---- stage 1: radix-8 over stride 64, twiddle W512^(t*s) via sincos powers ----
    dft8(v);
    {
        float sv, cv;
        __sincosf(-0.01227184630308513f * (float)lt, &sv, &cv);   // -2*pi/512 * lt
        float2 w1 = make_float2(cv, sv);
        float2 w = w1;
        v[1] = cmul(v[1], w);
        #pragma unroll
        for (int s = 2; s < 8; s++) { w = cmul(w, w1); v[s] = cmul(v[s], w); }
    }

    // exchange 1: store z_s[t] at 72*s + t ; read z_s[n'' + 8j']
    #pragma unroll
    for (int s = 0; s < 8; s++) sZ[grp][72 * s + lt] = v[s];
    __syncthreads();
    {
        const int s = lt >> 3, npp = lt & 7;
        #pragma unroll
        for (int j = 0; j < 8; j++) v[j] = sZ[grp][72 * s + npp + 8 * j];
        __syncthreads();

        // ---- stage 2: radix-8, twiddle W64^(n''*s') via sincos powers ----
        dft8(v);
        {
            float sv, cv;
            __sincosf(-0.0981747704246810f * (float)npp, &sv, &cv); // -2*pi/64 * npp
            float2 w1 = make_float2(cv, sv);
            float2 w = w1;
            v[1] = cmul(v[1], w);
            #pragma unroll
            for (int sp = 2; sp < 8; sp++) { w = cmul(w, w1); v[sp] = cmul(v[sp], w); }
        }

        // exchange 2: store at 66*n'' + 8*s' + s (conflict-free for float2)
        #pragma unroll
        for (int sp = 0; sp < 8; sp++) sZ[grp][66 * npp + 8 * sp + s] = v[sp];
    }
    __syncthreads();
    {
        const int sp = lt >> 3, s = lt & 7;
        #pragma unroll
        for (int j = 0; j < 8; j++) v[j] = sZ[grp][66 * j + 8 * sp + s];
        __syncthreads();

        // ---- stage 3: radix-8 -> X[64*m + lt] ----
        dft8(v);
        #pragma unroll
        for (int m = 0; m < 8; m++) sZ[grp][72 * m + lt] = v[m];
    }
    __syncthreads();

    // ---- unpack conjugate symmetry -> magnitudes for both frames ----
    for (int k = lt; k < NBIN; k += 64) {
        int a1 = 72 * (k >> 6) + (k & 63);
        int kk = (NFFT - k) & (NFFT - 1);
        int a2 = 72 * (kk >> 6) + (kk & 63);
        float2 u = sZ[grp][a1];
        float2 w = sZ[grp][a2];
        float Ar = 0.5f * (u.x + w.x), Ai = 0.5f * (u.y - w.y);
        float Br = 0.5f * (u.y + w.y), Bi = 0.5f * (w.x - u.x);
        sMag[grp][0][k] = sqrtf(Ar * Ar + Ai * Ai);
        sMag[grp][1][k] = sqrtf(Br * Br + Bi * Bi);
    }
    __syncthreads();

    // ---- mel filterbank + log (80 tasks over 64 threads) ----
    #pragma unroll
    for (int i = lt; i < 2 * NMELS; i += 64) {
        int fr = i / NMELS, m = i - fr * NMELS;
        const int klo = sKlo[m], len = sLen[m];
        const float* __restrict__ fw = sFbw + m * 33;
        const float* __restrict__ mg = sMag[grp][fr] + klo;
        float acc = 0.0f;
        for (int j = 0; j < len; j++) acc = fmaf(fw[j], mg[j], acc);
        sMel[grp][fr][m] = __logf(acc + 1e-20f);
    }
    __syncthreads();

    // ---- DCT-II ortho, 16 rows, split dot across thread pairs ----
    {
        int task = lt >> 1;                 // 0..31 = (fr, m)
        int half = lt & 1;
        int fr = task >> 4, m = task & 15;
        const float* __restrict__ dr = sDct + m * 41 + half * 20;
        const float* __restrict__ ml = sMel[grp][fr] + half * 20;
        float acc = 0.0f;
        #pragma unroll
        for (int n = 0; n < 20; n++) acc = fmaf(dr[n], ml[n], acc);
        acc += __shfl_xor_sync(0xffffffffu, acc, 1);
        if (half == 0) sMfcc[grp][fr][m] = acc;
    }
    __syncthreads();

    // ---- first delta over coefficients (valid for c<=14; we need c<=13) ----
    if (lt < 32) {
        int fr = lt >> 4, c = lt & 15;
        float val = 0.0f;
        if (c >= 1 && c <= 14) val = 0.5f * (sMfcc[grp][fr][c + 1] - sMfcc[grp][fr][c - 1]);
        sD1[grp][fr][c] = val;             // c==15 slot holds garbage-free 0; unused
    }
    __syncthreads();

    // ---- write [mfcc[0:13], d1[0:13], d2[0:13]] for both frames ----
    #pragma unroll
    for (int i = lt; i < 2 * OUTC; i += 64) {
        int fr = i / OUTC, c = i - fr * OUTC;
        int frame = b * NF + f0 + fr;
        float val;
        if (c < NMFCC) {
            val = sMfcc[grp][fr][c];
        } else if (c < 2 * NMFCC) {
            val = sD1[grp][fr][c - NMFCC];
        } else {
            int cc = c - 2 * NMFCC;
            val = (cc >= 1) ? 0.5f * (sD1[grp][fr][cc + 1] - sD1[grp][fr][cc - 1]) : 0.0f;
        }
        out[(size_t)frame * OUTC + c] = val;
    }
}

extern "C" void kernel_launch(void* const* d_in, const int* in_sizes, int n_in,
                              void* d_out, int out_size) {
    (void)in_sizes; (void)n_in; (void)out_size;
    const float* x = (const float*)d_in[0];
    float* out = (float*)d_out;
    init_consts_kernel<<<1, 256>>>();
    mfcc_kernel<<<NPAIR / GROUPS, THREADS>>>(x, out);
}